// round 11
// baseline (speedup 1.0000x reference)
#include <cuda_runtime.h>
#include <cuda_fp16.h>
#include <cstdint>

// ============================================================================
// NETWORK_OF_DANS — round 11: fragment double-buffering in the HMMA mainloop
//
// Same algorithm as round 10 (Dw1 folded into W' -> N=16384, fp16 HMMA,
// fused DAN tail, 2 CTAs/SM, k-phase stagger). New: A/B ldmatrix fragments
// are double-buffered with prefetch distance 1, so mma(ks) never RAW-waits
// on shared-memory latency (the ldsm<->mma alternation was capping tensor
// pipe at ~49%).
// ============================================================================

#define NTH 256
#define BM 128
#define BN 128
#define BK 64

// ---------------- scratch (fp16 bit patterns as ushort) ---------------------
__device__ unsigned short g_A0[512 * 1024];
__device__ unsigned short g_A1[512 * 2048];
__device__ unsigned short g_A2[512 * 2048];
__device__ unsigned short g_B0[16384 * 1024];
__device__ unsigned short g_B1[16384 * 2048];
__device__ unsigned short g_B2[16384 * 2048];

// ---------------- smem layout (dynamic) -------------------------------------
#define T_A 0                 // 128x64 fp16 = 16 KB
#define T_B 16384             // 128x64 fp16 = 16 KB
#define STG_SZ 32768
#define SM_B15  (3 * STG_SZ)              // 98304: 120 floats (8 nodes x 15)
#define SM_DW1  (SM_B15 + 512)
#define SM_DB1  (SM_DW1 + 1920)
#define SM_DW2  (SM_DB1 + 64)
#define SM_DB2  (SM_DW2 + 480)
#define SM_DW3  (SM_DB2 + 32)
#define SM_DB3  (SM_DW3 + 32)
#define SMEM_TOTAL (SM_DB3 + 16)          // ~101 KB -> 2 CTAs/SM

#define SWZ(o) ((o) ^ (((o) >> 3) & 0x70))

__device__ __forceinline__ uint32_t smem_u32(const void* p) {
    uint32_t a;
    asm("{ .reg .u64 t; cvta.to.shared.u64 t, %1; cvt.u32.u64 %0, t; }"
        : "=r"(a) : "l"(p));
    return a;
}
__device__ __forceinline__ float lrelu(float v) { return v > 0.0f ? v : 0.01f * v; }

__device__ __forceinline__ unsigned long long pack2(float lo, float hi) {
    unsigned long long r;
    asm("mov.b64 %0, {%1, %2};" : "=l"(r) : "f"(lo), "f"(hi));
    return r;
}
__device__ __forceinline__ void unpack2(unsigned long long v, float& lo, float& hi) {
    asm("mov.b64 {%0, %1}, %2;" : "=f"(lo), "=f"(hi) : "l"(v));
}
__device__ __forceinline__ void ffma2(unsigned long long& d, unsigned long long a,
                                      unsigned long long b) {
    asm("fma.rn.f32x2 %0, %1, %2, %3;" : "=l"(d) : "l"(a), "l"(b), "l"(d));
}

__device__ __forceinline__ void ldsm4(uint32_t* r, uint32_t a) {
    asm volatile("ldmatrix.sync.aligned.m8n8.x4.shared.b16 {%0,%1,%2,%3}, [%4];"
                 : "=r"(r[0]), "=r"(r[1]), "=r"(r[2]), "=r"(r[3]) : "r"(a));
}
__device__ __forceinline__ void mma16816(float* d, const uint32_t* a,
                                         const uint32_t* b) {
    asm volatile(
        "mma.sync.aligned.m16n8k16.row.col.f32.f16.f16.f32 "
        "{%0,%1,%2,%3}, {%4,%5,%6,%7}, {%8,%9}, {%0,%1,%2,%3};"
        : "+f"(d[0]), "+f"(d[1]), "+f"(d[2]), "+f"(d[3])
        : "r"(a[0]), "r"(a[1]), "r"(a[2]), "r"(a[3]), "r"(b[0]), "r"(b[1]));
}
__device__ __forceinline__ void cpa16(uint32_t s, const void* g) {
    asm volatile("cp.async.cg.shared.global [%0], [%1], 16;" :: "r"(s), "l"(g));
}
#define CP_COMMIT() asm volatile("cp.async.commit_group;" ::: "memory")
#define CP_WAIT(n)  asm volatile("cp.async.wait_group %0;" :: "n"(n) : "memory")

// ---------------------------------------------------------------------------
// Fold: W'[node*16+u, :] = sum_ch Dw1[u,ch] * W[node*32+ch, :], row 15 = 0.
// ---------------------------------------------------------------------------
struct FoldArgs {
    const float* src[5];
    unsigned short* dst[5];
    int ld[5];
    int off[5];
};

__global__ __launch_bounds__(256) void fold_w(FoldArgs fa, const float* __restrict__ Dw1g) {
    __shared__ float sDw[15 * 32];
    const int b = blockIdx.x;
    const int reg = b >> 10, node = b & 1023;
    const int tid = threadIdx.x;

    for (int i = tid; i < 15 * 32; i += 256)
        sDw[i] = Dw1g[(i >> 5) * 35 + (i & 31)];
    __syncthreads();

    const float* W = fa.src[reg] + (size_t)node * 32 * 1024 + tid * 4;

    unsigned long long acc2[15][2];
#pragma unroll
    for (int u = 0; u < 15; ++u) { acc2[u][0] = 0ULL; acc2[u][1] = 0ULL; }

#pragma unroll 2
    for (int ch = 0; ch < 32; ++ch) {
        float4 w = *(const float4*)(W + (size_t)ch * 1024);
        unsigned long long p0 = pack2(w.x, w.y), p1 = pack2(w.z, w.w);
#pragma unroll
        for (int u = 0; u < 15; ++u) {
            float dv = sDw[u * 32 + ch];
            unsigned long long d2 = pack2(dv, dv);
            ffma2(acc2[u][0], d2, p0);
            ffma2(acc2[u][1], d2, p1);
        }
    }

    const int ld = fa.ld[reg];
    unsigned short* dst = fa.dst[reg] + (size_t)(node * 16) * ld + fa.off[reg] + tid * 4;
#pragma unroll
    for (int u = 0; u < 15; ++u) {
        float a0, a1, a2, a3;
        unpack2(acc2[u][0], a0, a1);
        unpack2(acc2[u][1], a2, a3);
        __half2 h01 = __floats2half2_rn(a0, a1);
        __half2 h23 = __floats2half2_rn(a2, a3);
        uint2 v;
        v.x = *(uint32_t*)&h01; v.y = *(uint32_t*)&h23;
        *(uint2*)(dst + (size_t)u * ld) = v;
    }
    uint2 z; z.x = 0u; z.y = 0u;
    *(uint2*)(dst + (size_t)15 * ld) = z;     // padded channel
}

// ---------------------------------------------------------------------------
// x conversion: f32 [512,1024] -> fp16 into A0 (ld 1024) and A1 cols 1024..
// ---------------------------------------------------------------------------
__global__ __launch_bounds__(256) void conv_x(
    const float* __restrict__ x, unsigned short* __restrict__ dA0,
    unsigned short* __restrict__ dA1)
{
    int idx = blockIdx.x * 256 + threadIdx.x;   // grid 256 -> 65536 = 512*128
    int r = idx >> 7, c = idx & 127;
    const float4* s = (const float4*)(x + (size_t)r * 1024 + c * 8);
    float4 v0 = s[0], v1 = s[1];
    __half2 h0 = __floats2half2_rn(v0.x, v0.y);
    __half2 h1 = __floats2half2_rn(v0.z, v0.w);
    __half2 h2 = __floats2half2_rn(v1.x, v1.y);
    __half2 h3 = __floats2half2_rn(v1.z, v1.w);
    uint4 H;
    H.x = *(uint32_t*)&h0; H.y = *(uint32_t*)&h1;
    H.z = *(uint32_t*)&h2; H.w = *(uint32_t*)&h3;
    *(uint4*)(dA0 + (size_t)r * 1024 + c * 8) = H;
    *(uint4*)(dA1 + (size_t)r * 2048 + 1024 + c * 8) = H;
}

// ---------------------------------------------------------------------------
// Fused fp16 HMMA GEMM (vs folded W') + DAN tail epilogue.
// Grid (4, 128): bm = bx*128, bn = by*128 (8 original nodes per CTA).
// ---------------------------------------------------------------------------
__global__ __launch_bounds__(NTH, 2) void dan_gemm_kernel(
    const unsigned short* __restrict__ Ah, const unsigned short* __restrict__ Bh,
    int ldK, int nchunks,
    const float* __restrict__ bias1, const float* __restrict__ bias2,
    const float* __restrict__ Dw1, const float* __restrict__ Db1,
    const float* __restrict__ Dw2, const float* __restrict__ Db2,
    const float* __restrict__ Dw3, const float* __restrict__ Db3,
    int layer_idx, int mode,                       // 0: fp32 out; 1: fp16 h out
    float* __restrict__ outf,
    unsigned short* __restrict__ oh1, unsigned short* __restrict__ oh2)
{
    extern __shared__ __align__(1024) char smem[];
    const uint32_t sb = smem_u32(smem);
    const int tid = threadIdx.x;
    const int wid = tid >> 5, lane = tid & 31;
    const int wm = wid >> 2, wn = wid & 3;       // 2 x 4 warp grid
    const int bm = blockIdx.x * BM, bn = blockIdx.y * BN;
    const int n0 = bn >> 4;                      // base original-node id

    // ---- stage DAN weights ----
    float* sB15 = (float*)(smem + SM_B15);
    float* sDw1 = (float*)(smem + SM_DW1);
    float* sDb1 = (float*)(smem + SM_DB1);
    float* sDw2 = (float*)(smem + SM_DW2);
    float* sDb2 = (float*)(smem + SM_DB2);
    float* sDw3 = (float*)(smem + SM_DW3);
    float* sDb3 = (float*)(smem + SM_DB3);
    for (int i = tid; i < 15 * 32; i += NTH) sDw1[i] = Dw1[(i >> 5) * 35 + (i & 31)];
    if (tid < 15) sDb1[tid] = Db1[tid] + Dw1[tid * 35 + 32 + layer_idx];
    if (tid >= 32 && tid < 152) sDw2[tid - 32] = Dw2[tid - 32];
    if (tid >= 160 && tid < 168) sDb2[tid - 160] = Db2[tid - 160];
    if (tid >= 168 && tid < 176) sDw3[tid - 168] = Dw3[tid - 168];
    if (tid == 176) sDb3[0] = Db3[0];

#define LOAD_STAGE(t, s) do {                                                   \
        const uint32_t stg_ = sb + (s) * STG_SZ;                                \
        const int k0_ = (t) * BK;                                               \
        _Pragma("unroll")                                                       \
        for (int j = 0; j < 4; ++j) {        /* A: 1024 16B-chunks */           \
            int ci = tid + j * NTH;                                             \
            int row = ci >> 3, ch = ci & 7;                                     \
            cpa16(stg_ + T_A + SWZ(row * 128 + ch * 16),                        \
                  Ah + (size_t)(bm + row) * ldK + k0_ + ch * 8);                \
        }                                                                       \
        _Pragma("unroll")                                                       \
        for (int j = 0; j < 4; ++j) {        /* B: 1024 16B-chunks */           \
            int ci = tid + j * NTH;                                             \
            int row = ci >> 3, ch = ci & 7;                                     \
            cpa16(stg_ + T_B + SWZ(row * 128 + ch * 16),                        \
                  Bh + (size_t)(bn + row) * ldK + k0_ + ch * 8);                \
        }                                                                       \
    } while (0)

    // k-phase stagger for co-resident CTAs.
    const int koff = (blockIdx.y & 1) * (nchunks >> 1);
#define WRAP(t) ((t) >= nchunks ? (t) - nchunks : (t))

    // ---- accumulators + double-buffered fragments ----
    float acc[4][4][4];
#pragma unroll
    for (int i = 0; i < 4; i++)
#pragma unroll
        for (int j = 0; j < 4; j++)
#pragma unroll
            for (int k = 0; k < 4; k++) acc[i][j][k] = 0.0f;

    uint32_t aF[2][4][4], bF[2][2][4];

    const uint32_t baseA = (uint32_t)((wm * 64 + (lane & 15)) * 128);
    const uint32_t baseB = (uint32_t)((wn * 32 + ((lane >> 4) & 1) * 8 + (lane & 7)) * 128);
    const int xorv = lane & 7;
    const int chA = lane >> 4;          // 0/1
    const int chB = (lane >> 3) & 1;    // 0/1

#define LD_FRAG(buf, stg, ks) do {                                              \
        const uint32_t cA_ = (uint32_t)((((ks) * 2 + chA) ^ xorv) << 4);        \
        const uint32_t cB_ = (uint32_t)((((ks) * 2 + chB) ^ xorv) << 4);        \
        _Pragma("unroll")                                                       \
        for (int mt_ = 0; mt_ < 4; ++mt_)                                       \
            ldsm4(aF[buf][mt_], (stg) + T_A + baseA + mt_ * 2048 + cA_);        \
        _Pragma("unroll")                                                       \
        for (int p_ = 0; p_ < 2; ++p_)                                          \
            ldsm4(bF[buf][p_], (stg) + T_B + baseB + p_ * 2048 + cB_);          \
    } while (0)

    // ---- 3-stage pipeline ----
    LOAD_STAGE(WRAP(koff), 0); CP_COMMIT();
    LOAD_STAGE(WRAP(koff + 1), 1); CP_COMMIT();
    __syncthreads();     // sDw1/sDb1 visible for b15 fold below

    // ---- per-node 15-vector bias fold (overlaps first stage loads) ----
    if (tid < 120) {
        const int n = tid / 15, u = tid % 15;
        const int gn = (n0 + n) * 32;
        float s = sDb1[u];
#pragma unroll 4
        for (int ch = 0; ch < 32; ++ch) {
            float bt = bias1[gn + ch];
            if (bias2) bt += bias2[gn + ch];
            s = fmaf(sDw1[u * 32 + ch], bt, s);
        }
        sB15[n * 15 + u] = s;
    }

    for (int tt = 0; tt < nchunks; ++tt) {
        CP_WAIT(1);
        __syncthreads();

        const uint32_t stg = sb + (tt % 3) * STG_SZ;
        LD_FRAG(0, stg, 0);                     // ks=0 frags first (start mma asap)

        const int tn = tt + 2;
        if (tn < nchunks) { int sl = tn % 3; LOAD_STAGE(WRAP(tn + koff), sl); }
        CP_COMMIT();

#pragma unroll
        for (int ks = 0; ks < 4; ++ks) {
            const int cur = ks & 1, nxt = cur ^ 1;
            if (ks < 3) LD_FRAG(nxt, stg, ks + 1);   // prefetch next ks
#pragma unroll
            for (int mt = 0; mt < 4; ++mt)
#pragma unroll
                for (int nt = 0; nt < 4; ++nt)
                    mma16816(acc[mt][nt], aF[cur][mt], &bF[cur][nt >> 1][(nt & 1) * 2]);
        }
    }

    // ---- epilogue: stage warp tile (raw pre15), then per-lane DAN tail ----
    CP_WAIT(0);
    __syncthreads();

    float* ep = (float*)(smem + wid * 8448);   // [64][33] per warp (67.6KB)
    const int r0 = lane >> 2, c0 = (lane & 3) * 2;
#pragma unroll
    for (int mt = 0; mt < 4; ++mt)
#pragma unroll
        for (int nt = 0; nt < 4; ++nt) {
            int rr = mt * 16 + r0, cc = nt * 8 + c0;
            ep[rr * 33 + cc]           = acc[mt][nt][0];
            ep[rr * 33 + cc + 1]       = acc[mt][nt][1];
            ep[(rr + 8) * 33 + cc]     = acc[mt][nt][2];
            ep[(rr + 8) * 33 + cc + 1] = acc[mt][nt][3];
        }
    __syncwarp();

#pragma unroll
    for (int ln = 0; ln < 2; ++ln) {            // 2 nodes per warp
        const float* b15 = sB15 + (wn * 2 + ln) * 15;
        const int gnode = n0 + wn * 2 + ln;
#pragma unroll
        for (int rr = 0; rr < 2; ++rr) {
            const int r = lane * 2 + rr;
            const float* zr = ep + r * 33 + ln * 16;
            float h1v[15];
#pragma unroll
            for (int u = 0; u < 15; ++u) h1v[u] = lrelu(zr[u] + b15[u]);
            float o = sDb3[0];
#pragma unroll
            for (int v = 0; v < 8; ++v) {
                float s = sDb2[v];
#pragma unroll
                for (int u = 0; u < 15; ++u) s = fmaf(sDw2[v * 15 + u], h1v[u], s);
                o = fmaf(sDw3[v], lrelu(s), o);
            }
            o = lrelu(o);

            const int grow = bm + wm * 64 + r;
            if (mode == 0) {
                outf[(size_t)grow * 1024 + gnode] = o;
            } else {
                __half oh = __float2half_rn(o);
                unsigned short hb = *(unsigned short*)&oh;
                size_t di = (size_t)grow * 2048 + gnode;
                oh1[di] = hb;
                if (oh2) oh2[di + 1024] = hb;
            }
        }
    }
#undef LOAD_STAGE
#undef LD_FRAG
#undef WRAP
}

// ---------------------------------------------------------------------------
extern "C" void kernel_launch(void* const* d_in, const int* in_sizes, int n_in,
                              void* d_out, int out_size) {
    (void)in_sizes; (void)n_in; (void)out_size;
    const float* x    = (const float*)d_in[0];
    const float* W0   = (const float*)d_in[1];
    const float* b0   = (const float*)d_in[2];
    const float* W1   = (const float*)d_in[3];
    const float* b1   = (const float*)d_in[4];
    const float* W2   = (const float*)d_in[5];
    const float* b2   = (const float*)d_in[6];
    const float* Ws02 = (const float*)d_in[7];
    const float* bs02 = (const float*)d_in[8];
    const float* Ws13 = (const float*)d_in[9];
    const float* bs13 = (const float*)d_in[10];
    const float* Dw1  = (const float*)d_in[11];
    const float* Db1  = (const float*)d_in[12];
    const float* Dw2  = (const float*)d_in[13];
    const float* Db2  = (const float*)d_in[14];
    const float* Dw3  = (const float*)d_in[15];
    const float* Db3  = (const float*)d_in[16];
    float* out = (float*)d_out;

    unsigned short *A0, *A1, *A2, *B0, *B1, *B2;
    cudaGetSymbolAddress((void**)&A0, g_A0);
    cudaGetSymbolAddress((void**)&A1, g_A1);
    cudaGetSymbolAddress((void**)&A2, g_A2);
    cudaGetSymbolAddress((void**)&B0, g_B0);
    cudaGetSymbolAddress((void**)&B1, g_B1);
    cudaGetSymbolAddress((void**)&B2, g_B2);

    cudaFuncSetAttribute(dan_gemm_kernel,
                         cudaFuncAttributeMaxDynamicSharedMemorySize, SMEM_TOTAL);

    // fold all 5 weight matrices (5 regions x 1024 nodes)
    FoldArgs fa;
    fa.src[0] = W0;   fa.dst[0] = B0; fa.ld[0] = 1024; fa.off[0] = 0;
    fa.src[1] = W1;   fa.dst[1] = B1; fa.ld[1] = 2048; fa.off[1] = 0;
    fa.src[2] = Ws02; fa.dst[2] = B1; fa.ld[2] = 2048; fa.off[2] = 1024;
    fa.src[3] = W2;   fa.dst[3] = B2; fa.ld[3] = 2048; fa.off[3] = 0;
    fa.src[4] = Ws13; fa.dst[4] = B2; fa.ld[4] = 2048; fa.off[4] = 1024;
    fold_w<<<5 * 1024, 256>>>(fa, Dw1);
    conv_x<<<256, 256>>>(x, A0, A1);

    dim3 grid(4, 128), block(NTH);
    // layer 0: h0 = DAN(x @ W0'^T) -> A1[:, :1024], A2[:, 1024:]
    dan_gemm_kernel<<<grid, block, SMEM_TOTAL>>>(
        A0, B0, 1024, 16, b0, nullptr,
        Dw1, Db1, Dw2, Db2, Dw3, Db3, 0, 1, nullptr, A1, A2);
    // layer 1: h1 = DAN([h0|x] @ [W1|Ws02]'^T) -> A2[:, :1024]
    dan_gemm_kernel<<<grid, block, SMEM_TOTAL>>>(
        A1, B1, 2048, 32, b1, bs02,
        Dw1, Db1, Dw2, Db2, Dw3, Db3, 1, 1, nullptr, A2, nullptr);
    // layer 2: out = DAN([h1|h0] @ [W2|Ws13]'^T)
    dan_gemm_kernel<<<grid, block, SMEM_TOTAL>>>(
        A2, B2, 2048, 32, b2, bs13,
        Dw1, Db1, Dw2, Db2, Dw3, Db3, 2, 0, out, nullptr, nullptr);
}

// round 12
// speedup vs baseline: 1.0834x; 1.0834x over previous
#include <cuda_runtime.h>
#include <cuda_fp16.h>
#include <cstdint>

// ============================================================================
// NETWORK_OF_DANS — round 12: round-10 GEMM core (reverted) + co-scheduled fold
//
// Round-11 post-mortem: fragment double-buffering spills at the hard 128-reg
// cap (2 CTAs/SM x 256 thr x 128 = full RF) -> reverted to round-10 mainloop.
// New: the W1/Ws02/W2/Ws13 fold (independent of layer 0) is co-scheduled in
// the SAME launch as the layer-0 GEMM (grid = 512 gemm blocks + 4096 fold
// blocks), overlapping ~130us of DRAM-bound fold with tensor-bound GEMM.
// prep0 fuses fold(W0) + x->fp16 conversion.
// ============================================================================

#define NTH 256
#define BM 128
#define BN 128
#define BK 64

// ---------------- scratch (fp16 bit patterns as ushort) ---------------------
__device__ unsigned short g_A0[512 * 1024];
__device__ unsigned short g_A1[512 * 2048];
__device__ unsigned short g_A2[512 * 2048];
__device__ unsigned short g_B0[16384 * 1024];
__device__ unsigned short g_B1[16384 * 2048];
__device__ unsigned short g_B2[16384 * 2048];

// ---------------- smem layout (dynamic) -------------------------------------
#define T_A 0                 // 128x64 fp16 = 16 KB
#define T_B 16384             // 128x64 fp16 = 16 KB
#define STG_SZ 32768
#define SM_B15  (3 * STG_SZ)              // 98304: 120 floats (8 nodes x 15)
#define SM_DW1  (SM_B15 + 512)
#define SM_DB1  (SM_DW1 + 1920)
#define SM_DW2  (SM_DB1 + 64)
#define SM_DB2  (SM_DW2 + 480)
#define SM_DW3  (SM_DB2 + 32)
#define SM_DB3  (SM_DW3 + 32)
#define SMEM_TOTAL (SM_DB3 + 16)          // ~101 KB -> 2 CTAs/SM

#define SWZ(o) ((o) ^ (((o) >> 3) & 0x70))

__device__ __forceinline__ uint32_t smem_u32(const void* p) {
    uint32_t a;
    asm("{ .reg .u64 t; cvta.to.shared.u64 t, %1; cvt.u32.u64 %0, t; }"
        : "=r"(a) : "l"(p));
    return a;
}
__device__ __forceinline__ float lrelu(float v) { return v > 0.0f ? v : 0.01f * v; }

__device__ __forceinline__ unsigned long long pack2(float lo, float hi) {
    unsigned long long r;
    asm("mov.b64 %0, {%1, %2};" : "=l"(r) : "f"(lo), "f"(hi));
    return r;
}
__device__ __forceinline__ void unpack2(unsigned long long v, float& lo, float& hi) {
    asm("mov.b64 {%0, %1}, %2;" : "=f"(lo), "=f"(hi) : "l"(v));
}
__device__ __forceinline__ void ffma2(unsigned long long& d, unsigned long long a,
                                      unsigned long long b) {
    asm("fma.rn.f32x2 %0, %1, %2, %3;" : "=l"(d) : "l"(a), "l"(b), "l"(d));
}

__device__ __forceinline__ void ldsm4(uint32_t* r, uint32_t a) {
    asm volatile("ldmatrix.sync.aligned.m8n8.x4.shared.b16 {%0,%1,%2,%3}, [%4];"
                 : "=r"(r[0]), "=r"(r[1]), "=r"(r[2]), "=r"(r[3]) : "r"(a));
}
__device__ __forceinline__ void mma16816(float* d, const uint32_t* a,
                                         const uint32_t* b) {
    asm volatile(
        "mma.sync.aligned.m16n8k16.row.col.f32.f16.f16.f32 "
        "{%0,%1,%2,%3}, {%4,%5,%6,%7}, {%8,%9}, {%0,%1,%2,%3};"
        : "+f"(d[0]), "+f"(d[1]), "+f"(d[2]), "+f"(d[3])
        : "r"(a[0]), "r"(a[1]), "r"(a[2]), "r"(a[3]), "r"(b[0]), "r"(b[1]));
}
__device__ __forceinline__ void cpa16(uint32_t s, const void* g) {
    asm volatile("cp.async.cg.shared.global [%0], [%1], 16;" :: "r"(s), "l"(g));
}
#define CP_COMMIT() asm volatile("cp.async.commit_group;" ::: "memory")
#define CP_WAIT(n)  asm volatile("cp.async.wait_group %0;" :: "n"(n) : "memory")

// ---------------------------------------------------------------------------
// Fold body: W'[node*16+u, :] = sum_ch Dw1[u,ch] * W[node*32+ch, :], row15=0.
// 256 threads, thread handles 4 columns. sDw = 480-float smem scratch.
// ---------------------------------------------------------------------------
struct FoldArgs {
    const float* src[5];
    unsigned short* dst[5];
    int ld[5];
    int off[5];
};

__device__ __forceinline__ void fold_node(const FoldArgs& fa, int reg, int node,
                                          int tid, float* sDw,
                                          const float* __restrict__ Dw1g)
{
    for (int i = tid; i < 15 * 32; i += 256)
        sDw[i] = Dw1g[(i >> 5) * 35 + (i & 31)];
    __syncthreads();

    const float* W = fa.src[reg] + (size_t)node * 32 * 1024 + tid * 4;

    unsigned long long acc2[15][2];
#pragma unroll
    for (int u = 0; u < 15; ++u) { acc2[u][0] = 0ULL; acc2[u][1] = 0ULL; }

#pragma unroll 2
    for (int ch = 0; ch < 32; ++ch) {
        float4 w = *(const float4*)(W + (size_t)ch * 1024);
        unsigned long long p0 = pack2(w.x, w.y), p1 = pack2(w.z, w.w);
#pragma unroll
        for (int u = 0; u < 15; ++u) {
            float dv = sDw[u * 32 + ch];
            unsigned long long d2 = pack2(dv, dv);
            ffma2(acc2[u][0], d2, p0);
            ffma2(acc2[u][1], d2, p1);
        }
    }

    const int ld = fa.ld[reg];
    unsigned short* dst = fa.dst[reg] + (size_t)(node * 16) * ld + fa.off[reg] + tid * 4;
#pragma unroll
    for (int u = 0; u < 15; ++u) {
        float a0, a1, a2, a3;
        unpack2(acc2[u][0], a0, a1);
        unpack2(acc2[u][1], a2, a3);
        __half2 h01 = __floats2half2_rn(a0, a1);
        __half2 h23 = __floats2half2_rn(a2, a3);
        uint2 v;
        v.x = *(uint32_t*)&h01; v.y = *(uint32_t*)&h23;
        *(uint2*)(dst + (size_t)u * ld) = v;
    }
    uint2 z; z.x = 0u; z.y = 0u;
    *(uint2*)(dst + (size_t)15 * ld) = z;     // padded channel
}

// ---------------------------------------------------------------------------
// prep0: blocks [0,1024) fold W0 -> B0; blocks [1024,1280) convert x -> A0,A1.
// ---------------------------------------------------------------------------
__global__ __launch_bounds__(256) void prep0(
    FoldArgs fa, const float* __restrict__ Dw1g,
    const float* __restrict__ x, unsigned short* __restrict__ dA0,
    unsigned short* __restrict__ dA1)
{
    __shared__ float sDw[15 * 32];
    const int b = blockIdx.x;
    const int tid = threadIdx.x;

    if (b < 1024) {
        fold_node(fa, 0, b, tid, sDw, Dw1g);
        return;
    }

    int idx = (b - 1024) * 256 + tid;           // 65536 = 512*128
    int r = idx >> 7, c = idx & 127;
    const float4* s = (const float4*)(x + (size_t)r * 1024 + c * 8);
    float4 v0 = s[0], v1 = s[1];
    __half2 h0 = __floats2half2_rn(v0.x, v0.y);
    __half2 h1 = __floats2half2_rn(v0.z, v0.w);
    __half2 h2 = __floats2half2_rn(v1.x, v1.y);
    __half2 h3 = __floats2half2_rn(v1.z, v1.w);
    uint4 H;
    H.x = *(uint32_t*)&h0; H.y = *(uint32_t*)&h1;
    H.z = *(uint32_t*)&h2; H.w = *(uint32_t*)&h3;
    *(uint4*)(dA0 + (size_t)r * 1024 + c * 8) = H;
    *(uint4*)(dA1 + (size_t)r * 2048 + 1024 + c * 8) = H;
}

// ---------------------------------------------------------------------------
// Fused fp16 HMMA GEMM (round-10 mainloop) + DAN tail, with optional fold
// blocks co-scheduled at the grid tail (nfold blocks, regions reg_base..).
// gemm blocks: bid < ngemm; bx = bid&3 (batch), by = bid>>2 (node tile).
// ---------------------------------------------------------------------------
__global__ __launch_bounds__(NTH, 2) void dan_gemm_kernel(
    const unsigned short* __restrict__ Ah, const unsigned short* __restrict__ Bh,
    int ldK, int nchunks,
    const float* __restrict__ bias1, const float* __restrict__ bias2,
    const float* __restrict__ Dw1, const float* __restrict__ Db1,
    const float* __restrict__ Dw2, const float* __restrict__ Db2,
    const float* __restrict__ Dw3, const float* __restrict__ Db3,
    int layer_idx, int mode,                       // 0: fp32 out; 1: fp16 h out
    float* __restrict__ outf,
    unsigned short* __restrict__ oh1, unsigned short* __restrict__ oh2,
    int nfold, int reg_base, FoldArgs fa)
{
    extern __shared__ __align__(1024) char smem[];
    const int tid = threadIdx.x;
    const int ngemm = gridDim.x - nfold;

    if ((int)blockIdx.x >= ngemm) {               // ---- co-scheduled fold ----
        const int b = blockIdx.x - ngemm;
        fold_node(fa, reg_base + (b >> 10), b & 1023, tid, (float*)smem, Dw1);
        return;
    }

    const uint32_t sb = smem_u32(smem);
    const int wid = tid >> 5, lane = tid & 31;
    const int wm = wid >> 2, wn = wid & 3;       // 2 x 4 warp grid
    const int bx = blockIdx.x & 3, by = blockIdx.x >> 2;
    const int bm = bx * BM, bn = by * BN;
    const int n0 = bn >> 4;                      // base original-node id

    // ---- stage DAN weights ----
    float* sB15 = (float*)(smem + SM_B15);
    float* sDw1 = (float*)(smem + SM_DW1);
    float* sDb1 = (float*)(smem + SM_DB1);
    float* sDw2 = (float*)(smem + SM_DW2);
    float* sDb2 = (float*)(smem + SM_DB2);
    float* sDw3 = (float*)(smem + SM_DW3);
    float* sDb3 = (float*)(smem + SM_DB3);
    for (int i = tid; i < 15 * 32; i += NTH) sDw1[i] = Dw1[(i >> 5) * 35 + (i & 31)];
    if (tid < 15) sDb1[tid] = Db1[tid] + Dw1[tid * 35 + 32 + layer_idx];
    if (tid >= 32 && tid < 152) sDw2[tid - 32] = Dw2[tid - 32];
    if (tid >= 160 && tid < 168) sDb2[tid - 160] = Db2[tid - 160];
    if (tid >= 168 && tid < 176) sDw3[tid - 168] = Dw3[tid - 168];
    if (tid == 176) sDb3[0] = Db3[0];

#define LOAD_STAGE(t, s) do {                                                   \
        const uint32_t stg_ = sb + (s) * STG_SZ;                                \
        const int k0_ = (t) * BK;                                               \
        _Pragma("unroll")                                                       \
        for (int j = 0; j < 4; ++j) {        /* A: 1024 16B-chunks */           \
            int ci = tid + j * NTH;                                             \
            int row = ci >> 3, ch = ci & 7;                                     \
            cpa16(stg_ + T_A + SWZ(row * 128 + ch * 16),                        \
                  Ah + (size_t)(bm + row) * ldK + k0_ + ch * 8);                \
        }                                                                       \
        _Pragma("unroll")                                                       \
        for (int j = 0; j < 4; ++j) {        /* B: 1024 16B-chunks */           \
            int ci = tid + j * NTH;                                             \
            int row = ci >> 3, ch = ci & 7;                                     \
            cpa16(stg_ + T_B + SWZ(row * 128 + ch * 16),                        \
                  Bh + (size_t)(bn + row) * ldK + k0_ + ch * 8);                \
        }                                                                       \
    } while (0)

    // k-phase stagger for co-resident CTAs.
    const int koff = (by & 1) * (nchunks >> 1);
#define WRAP(t) ((t) >= nchunks ? (t) - nchunks : (t))

    // ---- accumulators ----
    float acc[4][4][4];
#pragma unroll
    for (int i = 0; i < 4; i++)
#pragma unroll
        for (int j = 0; j < 4; j++)
#pragma unroll
            for (int k = 0; k < 4; k++) acc[i][j][k] = 0.0f;

    const uint32_t baseA = (uint32_t)((wm * 64 + (lane & 15)) * 128);
    const uint32_t baseB = (uint32_t)((wn * 32 + ((lane >> 4) & 1) * 8 + (lane & 7)) * 128);
    const int xorv = lane & 7;
    const int chA = lane >> 4;          // 0/1
    const int chB = (lane >> 3) & 1;    // 0/1

    // ---- 3-stage pipeline ----
    LOAD_STAGE(WRAP(koff), 0); CP_COMMIT();
    LOAD_STAGE(WRAP(koff + 1), 1); CP_COMMIT();
    __syncthreads();     // sDw1/sDb1 visible for b15 fold below

    // ---- per-node 15-vector bias fold (overlaps first stage loads) ----
    if (tid < 120) {
        const int n = tid / 15, u = tid % 15;
        const int gn = (n0 + n) * 32;
        float s = sDb1[u];
#pragma unroll 4
        for (int ch = 0; ch < 32; ++ch) {
            float bt = bias1[gn + ch];
            if (bias2) bt += bias2[gn + ch];
            s = fmaf(sDw1[u * 32 + ch], bt, s);
        }
        sB15[n * 15 + u] = s;
    }

    for (int tt = 0; tt < nchunks; ++tt) {
        CP_WAIT(1);
        __syncthreads();
        const int tn = tt + 2;
        if (tn < nchunks) { int sl = tn % 3; LOAD_STAGE(WRAP(tn + koff), sl); }
        CP_COMMIT();

        const uint32_t stg = sb + (tt % 3) * STG_SZ;
#pragma unroll
        for (int ks = 0; ks < 4; ++ks) {
            const uint32_t cA = (uint32_t)(((ks * 2 + chA) ^ xorv) << 4);
            const uint32_t cB = (uint32_t)(((ks * 2 + chB) ^ xorv) << 4);
            uint32_t aF[4][4], bF[2][4];
#pragma unroll
            for (int mt = 0; mt < 4; ++mt)
                ldsm4(aF[mt], stg + T_A + baseA + mt * 2048 + cA);
#pragma unroll
            for (int p = 0; p < 2; ++p)
                ldsm4(bF[p], stg + T_B + baseB + p * 2048 + cB);
#pragma unroll
            for (int mt = 0; mt < 4; ++mt)
#pragma unroll
                for (int nt = 0; nt < 4; ++nt)
                    mma16816(acc[mt][nt], aF[mt], &bF[nt >> 1][(nt & 1) * 2]);
        }
    }

    // ---- epilogue: stage warp tile (raw pre15), then per-lane DAN tail ----
    CP_WAIT(0);
    __syncthreads();

    float* ep = (float*)(smem + wid * 8448);   // [64][33] per warp (67.6KB)
    const int r0 = lane >> 2, c0 = (lane & 3) * 2;
#pragma unroll
    for (int mt = 0; mt < 4; ++mt)
#pragma unroll
        for (int nt = 0; nt < 4; ++nt) {
            int rr = mt * 16 + r0, cc = nt * 8 + c0;
            ep[rr * 33 + cc]           = acc[mt][nt][0];
            ep[rr * 33 + cc + 1]       = acc[mt][nt][1];
            ep[(rr + 8) * 33 + cc]     = acc[mt][nt][2];
            ep[(rr + 8) * 33 + cc + 1] = acc[mt][nt][3];
        }
    __syncwarp();

#pragma unroll
    for (int ln = 0; ln < 2; ++ln) {            // 2 nodes per warp
        const float* b15 = sB15 + (wn * 2 + ln) * 15;
        const int gnode = n0 + wn * 2 + ln;
#pragma unroll
        for (int rr = 0; rr < 2; ++rr) {
            const int r = lane * 2 + rr;
            const float* zr = ep + r * 33 + ln * 16;
            float h1v[15];
#pragma unroll
            for (int u = 0; u < 15; ++u) h1v[u] = lrelu(zr[u] + b15[u]);
            float o = sDb3[0];
#pragma unroll
            for (int v = 0; v < 8; ++v) {
                float s = sDb2[v];
#pragma unroll
                for (int u = 0; u < 15; ++u) s = fmaf(sDw2[v * 15 + u], h1v[u], s);
                o = fmaf(sDw3[v], lrelu(s), o);
            }
            o = lrelu(o);

            const int grow = bm + wm * 64 + r;
            if (mode == 0) {
                outf[(size_t)grow * 1024 + gnode] = o;
            } else {
                __half oh = __float2half_rn(o);
                unsigned short hb = *(unsigned short*)&oh;
                size_t di = (size_t)grow * 2048 + gnode;
                oh1[di] = hb;
                if (oh2) oh2[di + 1024] = hb;
            }
        }
    }
#undef LOAD_STAGE
#undef WRAP
}

// ---------------------------------------------------------------------------
extern "C" void kernel_launch(void* const* d_in, const int* in_sizes, int n_in,
                              void* d_out, int out_size) {
    (void)in_sizes; (void)n_in; (void)out_size;
    const float* x    = (const float*)d_in[0];
    const float* W0   = (const float*)d_in[1];
    const float* b0   = (const float*)d_in[2];
    const float* W1   = (const float*)d_in[3];
    const float* b1   = (const float*)d_in[4];
    const float* W2   = (const float*)d_in[5];
    const float* b2   = (const float*)d_in[6];
    const float* Ws02 = (const float*)d_in[7];
    const float* bs02 = (const float*)d_in[8];
    const float* Ws13 = (const float*)d_in[9];
    const float* bs13 = (const float*)d_in[10];
    const float* Dw1  = (const float*)d_in[11];
    const float* Db1  = (const float*)d_in[12];
    const float* Dw2  = (const float*)d_in[13];
    const float* Db2  = (const float*)d_in[14];
    const float* Dw3  = (const float*)d_in[15];
    const float* Db3  = (const float*)d_in[16];
    float* out = (float*)d_out;

    unsigned short *A0, *A1, *A2, *B0, *B1, *B2;
    cudaGetSymbolAddress((void**)&A0, g_A0);
    cudaGetSymbolAddress((void**)&A1, g_A1);
    cudaGetSymbolAddress((void**)&A2, g_A2);
    cudaGetSymbolAddress((void**)&B0, g_B0);
    cudaGetSymbolAddress((void**)&B1, g_B1);
    cudaGetSymbolAddress((void**)&B2, g_B2);

    cudaFuncSetAttribute(dan_gemm_kernel,
                         cudaFuncAttributeMaxDynamicSharedMemorySize, SMEM_TOTAL);

    FoldArgs fa;
    fa.src[0] = W0;   fa.dst[0] = B0; fa.ld[0] = 1024; fa.off[0] = 0;
    fa.src[1] = W1;   fa.dst[1] = B1; fa.ld[1] = 2048; fa.off[1] = 0;
    fa.src[2] = Ws02; fa.dst[2] = B1; fa.ld[2] = 2048; fa.off[2] = 1024;
    fa.src[3] = W2;   fa.dst[3] = B2; fa.ld[3] = 2048; fa.off[3] = 0;
    fa.src[4] = Ws13; fa.dst[4] = B2; fa.ld[4] = 2048; fa.off[4] = 1024;

    // prep: fold W0 -> B0 (1024 blocks) + convert x -> A0, A1[:,1024:] (256)
    prep0<<<1280, 256>>>(fa, Dw1, x, A0, A1);

    // layer 0 GEMM (512 blocks) co-scheduled with fold of W1/Ws02/W2/Ws13
    // (4096 blocks, regions 1..4) in ONE launch.
    dan_gemm_kernel<<<512 + 4096, NTH, SMEM_TOTAL>>>(
        A0, B0, 1024, 16, b0, nullptr,
        Dw1, Db1, Dw2, Db2, Dw3, Db3, 0, 1, nullptr, A1, A2,
        4096, 1, fa);
    // layer 1: h1 = DAN([h0|x] @ [W1|Ws02]'^T) -> A2[:, :1024]
    dan_gemm_kernel<<<512, NTH, SMEM_TOTAL>>>(
        A1, B1, 2048, 32, b1, bs02,
        Dw1, Db1, Dw2, Db2, Dw3, Db3, 1, 1, nullptr, A2, nullptr,
        0, 0, fa);
    // layer 2: out = DAN([h1|h0] @ [W2|Ws13]'^T)
    dan_gemm_kernel<<<512, NTH, SMEM_TOTAL>>>(
        A2, B2, 2048, 32, b2, bs13,
        Dw1, Db1, Dw2, Db2, Dw3, Db3, 2, 0, out, nullptr, nullptr,
        0, 0, fa);
}

// round 13
// speedup vs baseline: 1.1560x; 1.0670x over previous
#include <cuda_runtime.h>
#include <cuda_fp16.h>
#include <cstdint>

// ============================================================================
// NETWORK_OF_DANS — round 13: fold pipelined across all 3 GEMM launches
//
// GEMM core is smem-crossbar-bound (96KB ldsm + 32KB sts per chunk per CTA
// x2 CTAs = 256KB/SM-chunk / 128B/cyc = 2048cyc = measured) -> unchanged.
// New: fold(W1,Ws02) rides with gemm0, fold(W2,Ws13) rides with gemm1
// (gemm_i never reads B_{i+1}), so ~190us of fold hides under ~240us of GEMM.
// Fold body batches 4 float4 loads (MLP 8 w/ unroll 2) for DRAM saturation.
// ============================================================================

#define NTH 256
#define BM 128
#define BN 128
#define BK 64

// ---------------- scratch (fp16 bit patterns as ushort) ---------------------
__device__ unsigned short g_A0[512 * 1024];
__device__ unsigned short g_A1[512 * 2048];
__device__ unsigned short g_A2[512 * 2048];
__device__ unsigned short g_B0[16384 * 1024];
__device__ unsigned short g_B1[16384 * 2048];
__device__ unsigned short g_B2[16384 * 2048];

// ---------------- smem layout (dynamic) -------------------------------------
#define T_A 0                 // 128x64 fp16 = 16 KB
#define T_B 16384             // 128x64 fp16 = 16 KB
#define STG_SZ 32768
#define SM_B15  (3 * STG_SZ)              // 98304: 120 floats (8 nodes x 15)
#define SM_DW1  (SM_B15 + 512)
#define SM_DB1  (SM_DW1 + 1920)
#define SM_DW2  (SM_DB1 + 64)
#define SM_DB2  (SM_DW2 + 480)
#define SM_DW3  (SM_DB2 + 32)
#define SM_DB3  (SM_DW3 + 32)
#define SMEM_TOTAL (SM_DB3 + 16)          // ~101 KB -> 2 CTAs/SM

#define SWZ(o) ((o) ^ (((o) >> 3) & 0x70))

__device__ __forceinline__ uint32_t smem_u32(const void* p) {
    uint32_t a;
    asm("{ .reg .u64 t; cvta.to.shared.u64 t, %1; cvt.u32.u64 %0, t; }"
        : "=r"(a) : "l"(p));
    return a;
}
__device__ __forceinline__ float lrelu(float v) { return v > 0.0f ? v : 0.01f * v; }

__device__ __forceinline__ unsigned long long pack2(float lo, float hi) {
    unsigned long long r;
    asm("mov.b64 %0, {%1, %2};" : "=l"(r) : "f"(lo), "f"(hi));
    return r;
}
__device__ __forceinline__ void unpack2(unsigned long long v, float& lo, float& hi) {
    asm("mov.b64 {%0, %1}, %2;" : "=f"(lo), "=f"(hi) : "l"(v));
}
__device__ __forceinline__ void ffma2(unsigned long long& d, unsigned long long a,
                                      unsigned long long b) {
    asm("fma.rn.f32x2 %0, %1, %2, %3;" : "=l"(d) : "l"(a), "l"(b), "l"(d));
}

__device__ __forceinline__ void ldsm4(uint32_t* r, uint32_t a) {
    asm volatile("ldmatrix.sync.aligned.m8n8.x4.shared.b16 {%0,%1,%2,%3}, [%4];"
                 : "=r"(r[0]), "=r"(r[1]), "=r"(r[2]), "=r"(r[3]) : "r"(a));
}
__device__ __forceinline__ void mma16816(float* d, const uint32_t* a,
                                         const uint32_t* b) {
    asm volatile(
        "mma.sync.aligned.m16n8k16.row.col.f32.f16.f16.f32 "
        "{%0,%1,%2,%3}, {%4,%5,%6,%7}, {%8,%9}, {%0,%1,%2,%3};"
        : "+f"(d[0]), "+f"(d[1]), "+f"(d[2]), "+f"(d[3])
        : "r"(a[0]), "r"(a[1]), "r"(a[2]), "r"(a[3]), "r"(b[0]), "r"(b[1]));
}
__device__ __forceinline__ void cpa16(uint32_t s, const void* g) {
    asm volatile("cp.async.cg.shared.global [%0], [%1], 16;" :: "r"(s), "l"(g));
}
#define CP_COMMIT() asm volatile("cp.async.commit_group;" ::: "memory")
#define CP_WAIT(n)  asm volatile("cp.async.wait_group %0;" :: "n"(n) : "memory")

// ---------------------------------------------------------------------------
// Fold body: W'[node*16+u, :] = sum_ch Dw1[u,ch] * W[node*32+ch, :], row15=0.
// 256 threads, thread handles 4 columns. Loads batched 4-wide for MLP.
// ---------------------------------------------------------------------------
struct FoldArgs {
    const float* src[5];
    unsigned short* dst[5];
    int ld[5];
    int off[5];
};

__device__ __forceinline__ void fold_node(const FoldArgs& fa, int reg, int node,
                                          int tid, float* sDw,
                                          const float* __restrict__ Dw1g)
{
    for (int i = tid; i < 15 * 32; i += 256)
        sDw[i] = Dw1g[(i >> 5) * 35 + (i & 31)];
    __syncthreads();

    const float* W = fa.src[reg] + (size_t)node * 32 * 1024 + tid * 4;

    unsigned long long acc2[15][2];
#pragma unroll
    for (int u = 0; u < 15; ++u) { acc2[u][0] = 0ULL; acc2[u][1] = 0ULL; }

#pragma unroll 2
    for (int cb = 0; cb < 32; cb += 4) {
        float4 w0 = *(const float4*)(W + (size_t)(cb + 0) * 1024);
        float4 w1 = *(const float4*)(W + (size_t)(cb + 1) * 1024);
        float4 w2 = *(const float4*)(W + (size_t)(cb + 2) * 1024);
        float4 w3 = *(const float4*)(W + (size_t)(cb + 3) * 1024);
        unsigned long long p[4][2] = {
            {pack2(w0.x, w0.y), pack2(w0.z, w0.w)},
            {pack2(w1.x, w1.y), pack2(w1.z, w1.w)},
            {pack2(w2.x, w2.y), pack2(w2.z, w2.w)},
            {pack2(w3.x, w3.y), pack2(w3.z, w3.w)}};
#pragma unroll
        for (int q = 0; q < 4; ++q)
#pragma unroll
            for (int u = 0; u < 15; ++u) {
                float dv = sDw[u * 32 + cb + q];
                unsigned long long d2 = pack2(dv, dv);
                ffma2(acc2[u][0], d2, p[q][0]);
                ffma2(acc2[u][1], d2, p[q][1]);
            }
    }

    const int ld = fa.ld[reg];
    unsigned short* dst = fa.dst[reg] + (size_t)(node * 16) * ld + fa.off[reg] + tid * 4;
#pragma unroll
    for (int u = 0; u < 15; ++u) {
        float a0, a1, a2, a3;
        unpack2(acc2[u][0], a0, a1);
        unpack2(acc2[u][1], a2, a3);
        __half2 h01 = __floats2half2_rn(a0, a1);
        __half2 h23 = __floats2half2_rn(a2, a3);
        uint2 v;
        v.x = *(uint32_t*)&h01; v.y = *(uint32_t*)&h23;
        *(uint2*)(dst + (size_t)u * ld) = v;
    }
    uint2 z; z.x = 0u; z.y = 0u;
    *(uint2*)(dst + (size_t)15 * ld) = z;     // padded channel
}

// ---------------------------------------------------------------------------
// prep0: blocks [0,1024) fold W0 -> B0; blocks [1024,1280) convert x -> A0,A1.
// ---------------------------------------------------------------------------
__global__ __launch_bounds__(256) void prep0(
    FoldArgs fa, const float* __restrict__ Dw1g,
    const float* __restrict__ x, unsigned short* __restrict__ dA0,
    unsigned short* __restrict__ dA1)
{
    __shared__ float sDw[15 * 32];
    const int b = blockIdx.x;
    const int tid = threadIdx.x;

    if (b < 1024) {
        fold_node(fa, 0, b, tid, sDw, Dw1g);
        return;
    }

    int idx = (b - 1024) * 256 + tid;           // 65536 = 512*128
    int r = idx >> 7, c = idx & 127;
    const float4* s = (const float4*)(x + (size_t)r * 1024 + c * 8);
    float4 v0 = s[0], v1 = s[1];
    __half2 h0 = __floats2half2_rn(v0.x, v0.y);
    __half2 h1 = __floats2half2_rn(v0.z, v0.w);
    __half2 h2 = __floats2half2_rn(v1.x, v1.y);
    __half2 h3 = __floats2half2_rn(v1.z, v1.w);
    uint4 H;
    H.x = *(uint32_t*)&h0; H.y = *(uint32_t*)&h1;
    H.z = *(uint32_t*)&h2; H.w = *(uint32_t*)&h3;
    *(uint4*)(dA0 + (size_t)r * 1024 + c * 8) = H;
    *(uint4*)(dA1 + (size_t)r * 2048 + 1024 + c * 8) = H;
}

// ---------------------------------------------------------------------------
// Fused fp16 HMMA GEMM + DAN tail, with fold blocks co-scheduled at the grid
// tail (nfold blocks, regions reg_base..). gemm blocks: bid < ngemm.
// ---------------------------------------------------------------------------
__global__ __launch_bounds__(NTH, 2) void dan_gemm_kernel(
    const unsigned short* __restrict__ Ah, const unsigned short* __restrict__ Bh,
    int ldK, int nchunks,
    const float* __restrict__ bias1, const float* __restrict__ bias2,
    const float* __restrict__ Dw1, const float* __restrict__ Db1,
    const float* __restrict__ Dw2, const float* __restrict__ Db2,
    const float* __restrict__ Dw3, const float* __restrict__ Db3,
    int layer_idx, int mode,                       // 0: fp32 out; 1: fp16 h out
    float* __restrict__ outf,
    unsigned short* __restrict__ oh1, unsigned short* __restrict__ oh2,
    int nfold, int reg_base, FoldArgs fa)
{
    extern __shared__ __align__(1024) char smem[];
    const int tid = threadIdx.x;
    const int ngemm = gridDim.x - nfold;

    if ((int)blockIdx.x >= ngemm) {               // ---- co-scheduled fold ----
        const int b = blockIdx.x - ngemm;
        fold_node(fa, reg_base + (b >> 10), b & 1023, tid, (float*)smem, Dw1);
        return;
    }

    const uint32_t sb = smem_u32(smem);
    const int wid = tid >> 5, lane = tid & 31;
    const int wm = wid >> 2, wn = wid & 3;       // 2 x 4 warp grid
    const int bx = blockIdx.x & 3, by = blockIdx.x >> 2;
    const int bm = bx * BM, bn = by * BN;
    const int n0 = bn >> 4;                      // base original-node id

    // ---- stage DAN weights ----
    float* sB15 = (float*)(smem + SM_B15);
    float* sDw1 = (float*)(smem + SM_DW1);
    float* sDb1 = (float*)(smem + SM_DB1);
    float* sDw2 = (float*)(smem + SM_DW2);
    float* sDb2 = (float*)(smem + SM_DB2);
    float* sDw3 = (float*)(smem + SM_DW3);
    float* sDb3 = (float*)(smem + SM_DB3);
    for (int i = tid; i < 15 * 32; i += NTH) sDw1[i] = Dw1[(i >> 5) * 35 + (i & 31)];
    if (tid < 15) sDb1[tid] = Db1[tid] + Dw1[tid * 35 + 32 + layer_idx];
    if (tid >= 32 && tid < 152) sDw2[tid - 32] = Dw2[tid - 32];
    if (tid >= 160 && tid < 168) sDb2[tid - 160] = Db2[tid - 160];
    if (tid >= 168 && tid < 176) sDw3[tid - 168] = Dw3[tid - 168];
    if (tid == 176) sDb3[0] = Db3[0];

#define LOAD_STAGE(t, s) do {                                                   \
        const uint32_t stg_ = sb + (s) * STG_SZ;                                \
        const int k0_ = (t) * BK;                                               \
        _Pragma("unroll")                                                       \
        for (int j = 0; j < 4; ++j) {        /* A: 1024 16B-chunks */           \
            int ci = tid + j * NTH;                                             \
            int row = ci >> 3, ch = ci & 7;                                     \
            cpa16(stg_ + T_A + SWZ(row * 128 + ch * 16),                        \
                  Ah + (size_t)(bm + row) * ldK + k0_ + ch * 8);                \
        }                                                                       \
        _Pragma("unroll")                                                       \
        for (int j = 0; j < 4; ++j) {        /* B: 1024 16B-chunks */           \
            int ci = tid + j * NTH;                                             \
            int row = ci >> 3, ch = ci & 7;                                     \
            cpa16(stg_ + T_B + SWZ(row * 128 + ch * 16),                        \
                  Bh + (size_t)(bn + row) * ldK + k0_ + ch * 8);                \
        }                                                                       \
    } while (0)

    // k-phase stagger for co-resident CTAs.
    const int koff = (by & 1) * (nchunks >> 1);
#define WRAP(t) ((t) >= nchunks ? (t) - nchunks : (t))

    // ---- accumulators ----
    float acc[4][4][4];
#pragma unroll
    for (int i = 0; i < 4; i++)
#pragma unroll
        for (int j = 0; j < 4; j++)
#pragma unroll
            for (int k = 0; k < 4; k++) acc[i][j][k] = 0.0f;

    const uint32_t baseA = (uint32_t)((wm * 64 + (lane & 15)) * 128);
    const uint32_t baseB = (uint32_t)((wn * 32 + ((lane >> 4) & 1) * 8 + (lane & 7)) * 128);
    const int xorv = lane & 7;
    const int chA = lane >> 4;          // 0/1
    const int chB = (lane >> 3) & 1;    // 0/1

    // ---- 3-stage pipeline ----
    LOAD_STAGE(WRAP(koff), 0); CP_COMMIT();
    LOAD_STAGE(WRAP(koff + 1), 1); CP_COMMIT();
    __syncthreads();     // sDw1/sDb1 visible for b15 fold below

    // ---- per-node 15-vector bias fold (overlaps first stage loads) ----
    if (tid < 120) {
        const int n = tid / 15, u = tid % 15;
        const int gn = (n0 + n) * 32;
        float s = sDb1[u];
#pragma unroll 4
        for (int ch = 0; ch < 32; ++ch) {
            float bt = bias1[gn + ch];
            if (bias2) bt += bias2[gn + ch];
            s = fmaf(sDw1[u * 32 + ch], bt, s);
        }
        sB15[n * 15 + u] = s;
    }

    for (int tt = 0; tt < nchunks; ++tt) {
        CP_WAIT(1);
        __syncthreads();
        const int tn = tt + 2;
        if (tn < nchunks) { int sl = tn % 3; LOAD_STAGE(WRAP(tn + koff), sl); }
        CP_COMMIT();

        const uint32_t stg = sb + (tt % 3) * STG_SZ;
#pragma unroll
        for (int ks = 0; ks < 4; ++ks) {
            const uint32_t cA = (uint32_t)(((ks * 2 + chA) ^ xorv) << 4);
            const uint32_t cB = (uint32_t)(((ks * 2 + chB) ^ xorv) << 4);
            uint32_t aF[4][4], bF[2][4];
#pragma unroll
            for (int mt = 0; mt < 4; ++mt)
                ldsm4(aF[mt], stg + T_A + baseA + mt * 2048 + cA);
#pragma unroll
            for (int p = 0; p < 2; ++p)
                ldsm4(bF[p], stg + T_B + baseB + p * 2048 + cB);
#pragma unroll
            for (int mt = 0; mt < 4; ++mt)
#pragma unroll
                for (int nt = 0; nt < 4; ++nt)
                    mma16816(acc[mt][nt], aF[mt], &bF[nt >> 1][(nt & 1) * 2]);
        }
    }

    // ---- epilogue: stage warp tile (raw pre15), then per-lane DAN tail ----
    CP_WAIT(0);
    __syncthreads();

    float* ep = (float*)(smem + wid * 8448);   // [64][33] per warp (67.6KB)
    const int r0 = lane >> 2, c0 = (lane & 3) * 2;
#pragma unroll
    for (int mt = 0; mt < 4; ++mt)
#pragma unroll
        for (int nt = 0; nt < 4; ++nt) {
            int rr = mt * 16 + r0, cc = nt * 8 + c0;
            ep[rr * 33 + cc]           = acc[mt][nt][0];
            ep[rr * 33 + cc + 1]       = acc[mt][nt][1];
            ep[(rr + 8) * 33 + cc]     = acc[mt][nt][2];
            ep[(rr + 8) * 33 + cc + 1] = acc[mt][nt][3];
        }
    __syncwarp();

#pragma unroll
    for (int ln = 0; ln < 2; ++ln) {            // 2 nodes per warp
        const float* b15 = sB15 + (wn * 2 + ln) * 15;
        const int gnode = n0 + wn * 2 + ln;
#pragma unroll
        for (int rr = 0; rr < 2; ++rr) {
            const int r = lane * 2 + rr;
            const float* zr = ep + r * 33 + ln * 16;
            float h1v[15];
#pragma unroll
            for (int u = 0; u < 15; ++u) h1v[u] = lrelu(zr[u] + b15[u]);
            float o = sDb3[0];
#pragma unroll
            for (int v = 0; v < 8; ++v) {
                float s = sDb2[v];
#pragma unroll
                for (int u = 0; u < 15; ++u) s = fmaf(sDw2[v * 15 + u], h1v[u], s);
                o = fmaf(sDw3[v], lrelu(s), o);
            }
            o = lrelu(o);

            const int grow = bm + wm * 64 + r;
            if (mode == 0) {
                outf[(size_t)grow * 1024 + gnode] = o;
            } else {
                __half oh = __float2half_rn(o);
                unsigned short hb = *(unsigned short*)&oh;
                size_t di = (size_t)grow * 2048 + gnode;
                oh1[di] = hb;
                if (oh2) oh2[di + 1024] = hb;
            }
        }
    }
#undef LOAD_STAGE
#undef WRAP
}

// ---------------------------------------------------------------------------
extern "C" void kernel_launch(void* const* d_in, const int* in_sizes, int n_in,
                              void* d_out, int out_size) {
    (void)in_sizes; (void)n_in; (void)out_size;
    const float* x    = (const float*)d_in[0];
    const float* W0   = (const float*)d_in[1];
    const float* b0   = (const float*)d_in[2];
    const float* W1   = (const float*)d_in[3];
    const float* b1   = (const float*)d_in[4];
    const float* W2   = (const float*)d_in[5];
    const float* b2   = (const float*)d_in[6];
    const float* Ws02 = (const float*)d_in[7];
    const float* bs02 = (const float*)d_in[8];
    const float* Ws13 = (const float*)d_in[9];
    const float* bs13 = (const float*)d_in[10];
    const float* Dw1  = (const float*)d_in[11];
    const float* Db1  = (const float*)d_in[12];
    const float* Dw2  = (const float*)d_in[13];
    const float* Db2  = (const float*)d_in[14];
    const float* Dw3  = (const float*)d_in[15];
    const float* Db3  = (const float*)d_in[16];
    float* out = (float*)d_out;

    unsigned short *A0, *A1, *A2, *B0, *B1, *B2;
    cudaGetSymbolAddress((void**)&A0, g_A0);
    cudaGetSymbolAddress((void**)&A1, g_A1);
    cudaGetSymbolAddress((void**)&A2, g_A2);
    cudaGetSymbolAddress((void**)&B0, g_B0);
    cudaGetSymbolAddress((void**)&B1, g_B1);
    cudaGetSymbolAddress((void**)&B2, g_B2);

    cudaFuncSetAttribute(dan_gemm_kernel,
                         cudaFuncAttributeMaxDynamicSharedMemorySize, SMEM_TOTAL);

    FoldArgs fa;
    fa.src[0] = W0;   fa.dst[0] = B0; fa.ld[0] = 1024; fa.off[0] = 0;
    fa.src[1] = W1;   fa.dst[1] = B1; fa.ld[1] = 2048; fa.off[1] = 0;
    fa.src[2] = Ws02; fa.dst[2] = B1; fa.ld[2] = 2048; fa.off[2] = 1024;
    fa.src[3] = W2;   fa.dst[3] = B2; fa.ld[3] = 2048; fa.off[3] = 0;
    fa.src[4] = Ws13; fa.dst[4] = B2; fa.ld[4] = 2048; fa.off[4] = 1024;

    // prep: fold W0 -> B0 (1024 blocks) + convert x -> A0, A1[:,1024:] (256)
    prep0<<<1280, 256>>>(fa, Dw1, x, A0, A1);

    // layer 0 GEMM co-scheduled with fold of W1/Ws02 (regions 1,2 -> B1)
    dan_gemm_kernel<<<512 + 2048, NTH, SMEM_TOTAL>>>(
        A0, B0, 1024, 16, b0, nullptr,
        Dw1, Db1, Dw2, Db2, Dw3, Db3, 0, 1, nullptr, A1, A2,
        2048, 1, fa);
    // layer 1 GEMM co-scheduled with fold of W2/Ws13 (regions 3,4 -> B2)
    dan_gemm_kernel<<<512 + 2048, NTH, SMEM_TOTAL>>>(
        A1, B1, 2048, 32, b1, bs02,
        Dw1, Db1, Dw2, Db2, Dw3, Db3, 1, 1, nullptr, A2, nullptr,
        2048, 3, fa);
    // layer 2: out = DAN([h1|h0] @ [W2|Ws13]'^T)
    dan_gemm_kernel<<<512, NTH, SMEM_TOTAL>>>(
        A2, B2, 2048, 32, b2, bs13,
        Dw1, Db1, Dw2, Db2, Dw3, Db3, 2, 0, out, nullptr, nullptr,
        0, 0, fa);
}